// round 4
// baseline (speedup 1.0000x reference)
#include <cuda_runtime.h>

#define BB 128
#define SS 512
#define KK 4
#define DD 300
#define CC 20
#define NN 10000
#define CHUNKS 8
#define SCHUNK (SS / CHUNKS)   // 64
#define SGRP 16
#define TPB (SGRP * CC)        // 320

// p_kernel tiling: thread = (node, class-group of 5, d-chunk of 100)
#define PD_TPB   128
#define PD_NODES 32                                  // nodes per block
#define DSPLIT   3
#define DCH      (DD / DSPLIT)                       // 100
#define PD_GRIDX ((NN + PD_NODES - 1) / PD_NODES)    // 313

// Scratch (deterministic, rewritten every call)
__device__ float g_Pp[DSPLIT][NN * CC];      // split-D partials (2.4 MB)
__device__ float g_P[NN * CC];               // P = node_emb @ fc_w^T (800 KB)
__device__ float g_part[BB * CHUNKS * CC];   // per-(b,chunk) logit partials

// ---------------------------------------------------------------------------
// K1: split-D partial GEMM.  Pp[dc][n,c] = sum_{d in chunk dc} E[n,d]*W[c,d]
// 120k threads (~25 warps/SM). Inner loop per 4 d: 1 LDG.128 + 5 LDS.128 + 20 FFMA.
// ---------------------------------------------------------------------------
__global__ void __launch_bounds__(PD_TPB) p_kernel(
    const float* __restrict__ node_emb, const float* __restrict__ fc_w)
{
    __shared__ float sF[CC * DCH];            // 8 KB, [c][d] d-contiguous

    const int t  = threadIdx.x;
    const int dc = blockIdx.y;
    const int d0 = dc * DCH;

    for (int i = t; i < CC * DCH; i += PD_TPB) {
        const int c = i / DCH, d = i % DCH;
        sF[i] = fc_w[c * DD + d0 + d];
    }
    __syncthreads();

    const int ng = t >> 2;                    // 0..31 node within block
    const int cg = t & 3;                     // 0..3  class-group (5 classes)
    const int n  = blockIdx.x * PD_NODES + ng;
    if (n >= NN) return;

    const float4* __restrict__ e4 = (const float4*)(node_emb + (size_t)n * DD + d0);
    const float4* __restrict__ f4 = (const float4*)(sF) + (cg * 5) * (DCH / 4);

    float acc[5] = {0.f, 0.f, 0.f, 0.f, 0.f};

    #pragma unroll 5
    for (int dq = 0; dq < DCH / 4; dq++) {    // 25 iters
        const float4 a = e4[dq];
        #pragma unroll
        for (int c5 = 0; c5 < 5; c5++) {
            const float4 fv = f4[c5 * (DCH / 4) + dq];
            acc[c5] += a.x * fv.x + a.y * fv.y + a.z * fv.z + a.w * fv.w;
        }
    }

    #pragma unroll
    for (int c5 = 0; c5 < 5; c5++)
        g_Pp[dc][n * CC + cg * 5 + c5] = acc[c5];
}

// ---------------------------------------------------------------------------
// K1b: reduce split-D partials (fixed order -> deterministic)
// ---------------------------------------------------------------------------
__global__ void __launch_bounds__(256) p_reduce_kernel()
{
    const int i = blockIdx.x * 256 + threadIdx.x;
    if (i < NN * CC)
        g_P[i] = g_Pp[0][i] + g_Pp[1][i] + g_Pp[2][i];
}

// ---------------------------------------------------------------------------
// K2: per-(b, s-chunk) logit partials via 80B gathers on P
// ---------------------------------------------------------------------------
__global__ void __launch_bounds__(TPB) gather_kernel(
    const int* __restrict__ X, const int* __restrict__ NX, const int* __restrict__ EW,
    const float* __restrict__ edge_w, const float* __restrict__ node_w)
{
    __shared__ int   sX[SCHUNK];
    __shared__ float sNW[SCHUNK];
    __shared__ int   sNX[SCHUNK * KK];
    __shared__ float sEW[SCHUNK * KK];
    __shared__ float sred[SGRP][CC];

    const int b  = blockIdx.y;
    const int ch = blockIdx.x;
    const int s0 = ch * SCHUNK;
    const int t  = threadIdx.x;

    if (t < SCHUNK) {
        int x = X[b * SS + s0 + t];
        sX[t]  = x;
        sNW[t] = node_w[x];
    }
    for (int i = t; i < SCHUNK * KK; i += TPB) sNX[i] = NX[(b * SS + s0) * KK + i];
    for (int i = t; i < SCHUNK * KK; i += TPB) sEW[i] = edge_w[EW[(b * SS + s0) * KK + i]];
    __syncthreads();

    const int g = t / CC, c = t % CC;
    float acc = 0.f;
    #pragma unroll
    for (int i = 0; i < SCHUNK / SGRP; i++) {
        const int s  = g + i * SGRP;
        const float nw = sNW[s];
        float m = 0.f;
        #pragma unroll
        for (int k = 0; k < KK; k++)
            m += sEW[s * KK + k] * __ldg(&g_P[sNX[s * KK + k] * CC + c]);
        acc += (1.f - nw) * m + nw * __ldg(&g_P[sX[s] * CC + c]);
    }
    sred[g][c] = acc;
    __syncthreads();

    #pragma unroll
    for (int off = SGRP / 2; off > 0; off >>= 1) {
        if (g < off) sred[g][c] += sred[g + off][c];
        __syncthreads();
    }
    if (g == 0) g_part[(b * CHUNKS + ch) * CC + c] = sred[0][c];
}

// ---------------------------------------------------------------------------
// K3: reduce chunk partials, add bias, relu, softmax
// ---------------------------------------------------------------------------
__global__ void __launch_bounds__(32) head_kernel(
    const float* __restrict__ fc_b, float* __restrict__ out)
{
    const int b = blockIdx.x, t = threadIdx.x;

    float v = -1e30f, l = 0.f;
    if (t < CC) {
        float s = fc_b[t];
        #pragma unroll
        for (int ch = 0; ch < CHUNKS; ch++)
            s += g_part[(b * CHUNKS + ch) * CC + t];
        l = fmaxf(s, 0.f);
        v = l;
    }
    float mx = v;
    #pragma unroll
    for (int o = 16; o; o >>= 1) mx = fmaxf(mx, __shfl_xor_sync(0xffffffffu, mx, o));
    float e = (t < CC) ? __expf(l - mx) : 0.f;
    float sum = e;
    #pragma unroll
    for (int o = 16; o; o >>= 1) sum += __shfl_xor_sync(0xffffffffu, sum, o);
    if (t < CC) out[b * CC + t] = e / sum;
}

// ---------------------------------------------------------------------------
extern "C" void kernel_launch(void* const* d_in, const int* in_sizes, int n_in,
                              void* d_out, int out_size)
{
    const int*   X        = (const int*)  d_in[0];
    const int*   NX       = (const int*)  d_in[1];
    const int*   EW       = (const int*)  d_in[2];
    const float* node_emb = (const float*)d_in[3];
    const float* edge_w   = (const float*)d_in[4];
    const float* node_w   = (const float*)d_in[5];
    const float* fc_w     = (const float*)d_in[6];
    const float* fc_b     = (const float*)d_in[7];
    float* out = (float*)d_out;

    dim3 grid1(PD_GRIDX, DSPLIT);
    p_kernel<<<grid1, PD_TPB>>>(node_emb, fc_w);
    p_reduce_kernel<<<(NN * CC + 255) / 256, 256>>>();
    dim3 grid2(CHUNKS, BB);
    gather_kernel<<<grid2, TPB>>>(X, NX, EW, edge_w, node_w);
    head_kernel<<<BB, 32>>>(fc_b, out);
}